// round 2
// baseline (speedup 1.0000x reference)
#include <cuda_runtime.h>

#define T_TOK 131072
#define Dd 256
#define NPROTO 512
#define BM 128
#define NBLK (T_TOK / BM)          // 1024 blocks
#define XS 260                      // padded x-tile row stride (floats)
#define WROW 132                    // padded w-tile row stride (floats)
#define TDTOT ((size_t)T_TOK * Dd)  // 33554432
#define TAU 0.02f                   // near-tie flag threshold (noise ~1e-4)

__device__ float g_wn[NPROTO];        // ||w_j||^2 (fp32-rounded double sum)
__device__ float g_partials[NBLK];    // per-block loss partials (non-flagged tokens)
__device__ float g_extra[T_TOK];      // per-flagged-token loss contribution
__device__ int   g_flaglist[T_TOK];   // flagged token ids
__device__ int   g_nflag;             // flagged count (reset each launch)

// ---- packed f32x2 helpers ----
__device__ __forceinline__ unsigned long long pk2(float lo, float hi) {
    unsigned long long r;
    asm("mov.b64 %0, {%1,%2};" : "=l"(r) : "f"(lo), "f"(hi));
    return r;
}
__device__ __forceinline__ void upk2(unsigned long long v, float& lo, float& hi) {
    asm("mov.b64 {%0,%1}, %2;" : "=f"(lo), "=f"(hi) : "l"(v));
}
__device__ __forceinline__ unsigned long long ffma2(unsigned long long a,
                                                    unsigned long long b,
                                                    unsigned long long c) {
    unsigned long long d;
    asm("fma.rn.f32x2 %0, %1, %2, %3;" : "=l"(d) : "l"(a), "l"(b), "l"(c));
    return d;
}

// ---- ||w_j||^2 (double-accumulated, fp32-rounded) + counter reset ----
__global__ void wn_kernel(const float* __restrict__ pw) {
    int j = blockIdx.x * blockDim.x + threadIdx.x;
    if (j == 0) g_nflag = 0;
    if (j < NPROTO) {
        const float* r = pw + (size_t)j * Dd;
        double s = 0.0;
        #pragma unroll 8
        for (int k = 0; k < Dd; k++) s += (double)r[k] * (double)r[k];
        g_wn[j] = (float)s;
    }
}

// ---- fused: distances + argmin(+2nd best) + gather + outputs + loss partial ----
__global__ __launch_bounds__(256) void vq_main(const float* __restrict__ x,
                                               const float* __restrict__ pw,
                                               float* __restrict__ out) {
    extern __shared__ float smem[];
    float* xs   = smem;                   // [BM][XS]  x tile
    float* wsm  = xs + BM * XS;           // [16][WROW] transposed W k-chunk
    float* wns  = wsm + 16 * WROW;        // [NPROTO]
    float* redv = wns + NPROTO;           // [BM][16] best vals
    float* red2 = redv + BM * 16;         // [BM][16] 2nd-best vals
    int*   redi = (int*)(red2 + BM * 16); // [BM][16] best idx
    int*   idxs = redi + BM * 16;         // [BM] final idx
    int*   flg  = idxs + BM;              // [BM] near-tie flag

    const int tid = threadIdx.x;
    const int tx = tid & 15;
    const int ty = tid >> 4;
    const int bm = blockIdx.x * BM;

    const float4* x4 = (const float4*)x;
    for (int e = tid; e < BM * (Dd / 4); e += 256) {
        int r = e >> 6, c4 = e & 63;
        float4 v = x4[(size_t)(bm + r) * (Dd / 4) + c4];
        *(float4*)&xs[r * XS + c4 * 4] = v;
    }
    for (int e = tid; e < NPROTO; e += 256) wns[e] = g_wn[e];
    __syncthreads();

    float bestv[8], best2[8];
    int   besti[8];
    #pragma unroll
    for (int i = 0; i < 8; i++) { bestv[i] = 3.0e38f; best2[i] = 3.0e38f; besti[i] = 0; }

    for (int nt = 0; nt < 4; nt++) {
        unsigned long long acc[8][4];
        #pragma unroll
        for (int i = 0; i < 8; i++)
            #pragma unroll
            for (int c = 0; c < 4; c++) acc[i][c] = 0ull;

        for (int kt = 0; kt < Dd / 16; kt++) {
            __syncthreads();
            #pragma unroll
            for (int it = 0; it < 8; it++) {
                int e = tid + it * 256;
                int jj = e >> 4, kk = e & 15;
                wsm[kk * WROW + jj] = pw[(size_t)(nt * 128 + jj) * Dd + kt * 16 + kk];
            }
            __syncthreads();
            const int kbase = kt * 16;
            #pragma unroll
            for (int kk = 0; kk < 16; kk++) {
                unsigned long long b2[4];
                #pragma unroll
                for (int c = 0; c < 4; c++)
                    b2[c] = *(const unsigned long long*)&wsm[kk * WROW + c * 32 + tx * 2];
                #pragma unroll
                for (int i = 0; i < 8; i++) {
                    float a = xs[(i * 16 + ty) * XS + kbase + kk];
                    unsigned long long a2 = pk2(a, a);
                    #pragma unroll
                    for (int c = 0; c < 4; c++) acc[i][c] = ffma2(a2, b2[c], acc[i][c]);
                }
            }
        }
        #pragma unroll
        for (int i = 0; i < 8; i++) {
            #pragma unroll
            for (int c = 0; c < 4; c++) {
                float d0, d1;
                upk2(acc[i][c], d0, d1);
                int j0 = nt * 128 + c * 32 + tx * 2;
                float s0 = wns[j0]     - 2.f * d0;
                float s1 = wns[j0 + 1] - 2.f * d1;
                if (s0 < bestv[i]) { best2[i] = bestv[i]; bestv[i] = s0; besti[i] = j0; }
                else if (s0 < best2[i]) best2[i] = s0;
                if (s1 < bestv[i]) { best2[i] = bestv[i]; bestv[i] = s1; besti[i] = j0 + 1; }
                else if (s1 < best2[i]) best2[i] = s1;
            }
        }
    }

    #pragma unroll
    for (int i = 0; i < 8; i++) {
        redv[(i * 16 + ty) * 16 + tx] = bestv[i];
        red2[(i * 16 + ty) * 16 + tx] = best2[i];
        redi[(i * 16 + ty) * 16 + tx] = besti[i];
    }
    __syncthreads();
    if (tid < BM) {
        float B1 = redv[tid * 16], B2 = red2[tid * 16];
        int   I1 = redi[tid * 16];
        #pragma unroll
        for (int t = 1; t < 16; t++) {
            float v1 = redv[tid * 16 + t];
            float v2 = red2[tid * 16 + t];
            int   ix = redi[tid * 16 + t];
            if (v1 < B1) { B2 = fminf(B1, v2); B1 = v1; I1 = ix; }
            else {
                if (v1 == B1 && ix < I1) I1 = ix;
                B2 = fminf(B2, v1);
            }
        }
        idxs[tid] = I1;
        int f = (B2 - B1 < TAU) ? 1 : 0;
        flg[tid] = f;
        if (f) {
            int slot = atomicAdd(&g_nflag, 1);
            g_flaglist[slot] = bm + tid;
        }
    }
    __syncthreads();

    // Epilogue: outputs for all rows; loss partial excludes flagged rows
    float lsum = 0.f;
    float4* outP = (float4*)out;
    float4* outX = outP + TDTOT / 4;
    const float4* w4 = (const float4*)pw;
    for (int e = tid; e < BM * 64; e += 256) {
        int r = e >> 6, c4 = e & 63;
        int j = idxs[r];
        float4 wv = __ldg(&w4[j * 64 + c4]);
        float4 xv = *(const float4*)&xs[r * XS + c4 * 4];
        size_t o = (size_t)(bm + r) * 64 + c4;
        outP[o] = wv;
        float4 dx;
        dx.x = xv.x - wv.x; dx.y = xv.y - wv.y;
        dx.z = xv.z - wv.z; dx.w = xv.w - wv.w;
        outX[o] = dx;
        if (!flg[r])
            lsum += dx.x * dx.x + dx.y * dx.y + dx.z * dx.z + dx.w * dx.w;
    }
    #pragma unroll
    for (int s = 16; s > 0; s >>= 1) lsum += __shfl_down_sync(0xffffffffu, lsum, s);
    __syncthreads();
    if ((tid & 31) == 0) redv[tid >> 5] = lsum;
    __syncthreads();
    if (tid == 0) {
        float t = 0.f;
        #pragma unroll
        for (int w = 0; w < 8; w++) t += redv[w];
        g_partials[blockIdx.x] = t;
    }
}

// ---- phase 2: resolve flagged tokens with double-precision dots +
//      fp32 emulation of the reference pipeline ----
__global__ __launch_bounds__(256) void fix_ties(const float* __restrict__ x,
                                                const float* __restrict__ pw,
                                                float* __restrict__ out) {
    __shared__ float xrow[Dd];
    __shared__ float rv[256];
    __shared__ int   ri[256];
    __shared__ double dred[8];
    const int tid = threadIdx.x;
    const int nf = g_nflag;

    for (int f = blockIdx.x; f < nf; f += gridDim.x) {
        const int t = g_flaglist[f];
        xrow[tid] = x[(size_t)t * Dd + tid];
        __syncthreads();

        // s_x: double-accumulated, fp32-rounded (centered on ref's fp32 value)
        double px = (double)xrow[tid] * (double)xrow[tid];
        #pragma unroll
        for (int s = 16; s > 0; s >>= 1)
            px += __shfl_down_sync(0xffffffffu, px, s);
        if ((tid & 31) == 0) dred[tid >> 5] = px;
        __syncthreads();
        float sx;
        {
            double t2 = 0.0;
            #pragma unroll
            for (int w = 0; w < 8; w++) t2 += dred[w];
            sx = (float)t2;
        }

        // exact dots for j = tid and j = tid + 256
        const float* w0 = pw + (size_t)tid * Dd;
        const float* w1 = pw + (size_t)(tid + 256) * Dd;
        double d0 = 0.0, d1 = 0.0;
        #pragma unroll 8
        for (int k = 0; k < Dd; k++) {
            double xv = (double)xrow[k];
            d0 += xv * (double)w0[k];
            d1 += xv * (double)w1[k];
        }
        // emulate: dist = fl(fl(s_x + s_w) - 2*fl(dot));  2*m is exact in fp32
        float dist0 = __fsub_rn(__fadd_rn(sx, g_wn[tid]),       2.0f * (float)d0);
        float dist1 = __fsub_rn(__fadd_rn(sx, g_wn[tid + 256]), 2.0f * (float)d1);
        float bv; int bi;
        if (dist1 < dist0) { bv = dist1; bi = tid + 256; }
        else               { bv = dist0; bi = tid; }
        rv[tid] = bv; ri[tid] = bi;
        __syncthreads();
        for (int s = 128; s > 0; s >>= 1) {
            if (tid < s) {
                float v = rv[tid + s]; int ix = ri[tid + s];
                if (v < rv[tid] || (v == rv[tid] && ix < ri[tid])) {
                    rv[tid] = v; ri[tid] = ix;
                }
            }
            __syncthreads();
        }
        const int j = ri[0];
        __syncthreads();

        // overwrite outputs for this token, record loss contribution
        float wv = pw[(size_t)j * Dd + tid];
        out[(size_t)t * Dd + tid] = wv;
        float dx = xrow[tid] - wv;
        out[TDTOT + (size_t)t * Dd + tid] = dx;
        rv[tid] = dx * dx;
        __syncthreads();
        for (int s = 128; s > 0; s >>= 1) {
            if (tid < s) rv[tid] += rv[tid + s];
            __syncthreads();
        }
        if (tid == 0) g_extra[t] = rv[0];
        __syncthreads();
    }
}

// ---- deterministic final loss reduction ----
__global__ void finalize_loss(float* __restrict__ out) {
    __shared__ float s[256];
    int tid = threadIdx.x;
    float v = 0.f;
    for (int t = tid; t < NBLK; t += 256) v += g_partials[t];
    for (int t = tid; t < T_TOK; t += 256) v += g_extra[t];
    s[tid] = v;
    __syncthreads();
    for (int st = 128; st > 0; st >>= 1) {
        if (tid < st) s[tid] += s[tid + st];
        __syncthreads();
    }
    if (tid == 0) out[2 * TDTOT] = s[0] * (1.25f / (float)TDTOT);
}

extern "C" void kernel_launch(void* const* d_in, const int* in_sizes, int n_in,
                              void* d_out, int out_size) {
    const float* x  = (const float*)d_in[0];
    const float* pw = (const float*)d_in[1];
    float* out = (float*)d_out;

    const int smem_bytes = (BM * XS + 16 * WROW + NPROTO + 2 * BM * 16) * 4
                         + BM * 16 * 4   // redi
                         + BM * 4        // idxs
                         + BM * 4;       // flg
    cudaFuncSetAttribute(vq_main, cudaFuncAttributeMaxDynamicSharedMemorySize, smem_bytes);

    wn_kernel<<<2, 256>>>(pw);
    vq_main<<<NBLK, 256, smem_bytes>>>(x, pw, out);
    fix_ties<<<256, 256>>>(x, pw, out);
    finalize_loss<<<1, 256>>>(out);
}

// round 5
// speedup vs baseline: 2.1333x; 2.1333x over previous
#include <cuda_runtime.h>
#include <cuda_bf16.h>
#include <cstdint>
#include <mma.h>

using namespace nvcuda;

#define T_TOK 131072
#define Dd 256
#define NPROTO 512
#define BM 128
#define NBLK (T_TOK / BM)           // 1024
#define TDTOT ((size_t)T_TOK * Dd)  // 33554432
#define TAU 0.5f                    // bf16 screen noise ~0.05 -> 10 sigma
#define CAND_CUT 2e-3f              // fp32 tier-1 noise ~3e-5 -> 60 sigma
#define FIXB 8
#define MAXC 16

#define ASTR 264                    // bf16 row stride (528B, mult of 16B)
#define SSTR 72                     // score row stride (288B, mult of 16B)

// smem byte offsets
#define SM_A    0                   // 128*264*2 = 67584
#define SM_B    67584               // 128*264*2 = 67584
#define SM_SC   135168              // 8*32*72*4 = 73728
#define SM_WNS  208896              // 2048
#define SM_RV   210944              // 1024
#define SM_R2   211968              // 1024
#define SM_RI   212992              // 1024
#define SM_IDX  214016              // 512
#define SM_FLG  214528              // 512
#define SMEMB   215040

typedef unsigned int u32;

__device__ float g_wn[NPROTO];
__device__ float g_partials[NBLK];
__device__ float g_epart[256];
__device__ float g_extra[T_TOK];
__device__ int   g_flaglist[T_TOK];
__device__ int   g_nflag;

// Stage a 128x256 fp32 tile as bf16 rows (stride ASTR) into smem.
__device__ __forceinline__ void stage_bf16(__nv_bfloat16* dst, const float4* __restrict__ s4,
                                           size_t row0, int tid) {
    for (int e = tid; e < 4096; e += 256) {
        int r = e >> 5, c8 = e & 31;
        const float4* p = s4 + (row0 + r) * 64 + c8 * 2;
        float4 a = p[0], b = p[1];
        __nv_bfloat162 q0 = __floats2bfloat162_rn(a.x, a.y);
        __nv_bfloat162 q1 = __floats2bfloat162_rn(a.z, a.w);
        __nv_bfloat162 q2 = __floats2bfloat162_rn(b.x, b.y);
        __nv_bfloat162 q3 = __floats2bfloat162_rn(b.z, b.w);
        uint4 v;
        v.x = *(u32*)&q0; v.y = *(u32*)&q1; v.z = *(u32*)&q2; v.w = *(u32*)&q3;
        *(uint4*)(dst + r * ASTR + c8 * 8) = v;   // 528B row stride -> 16B aligned
    }
}

// ---- ||w||^2 (fp64-accumulated, fp32-rounded) + flag counter reset ----
__global__ void wn_kernel(const float* __restrict__ pw) {
    int j = blockIdx.x * blockDim.x + threadIdx.x;
    if (j == 0) g_nflag = 0;
    if (j < NPROTO) {
        const float* r = pw + (size_t)j * Dd;
        double s = 0.0;
        #pragma unroll 8
        for (int k = 0; k < Dd; k++) s += (double)r[k] * (double)r[k];
        g_wn[j] = (float)s;
    }
}

// ---- main fused kernel: wmma bf16 screen + argmin + flag + outputs ----
__global__ __launch_bounds__(256) void vq_main(const float* __restrict__ x,
                                               const float* __restrict__ pw,
                                               float* __restrict__ out) {
    extern __shared__ char smem[];
    __nv_bfloat16* As = (__nv_bfloat16*)(smem + SM_A);
    __nv_bfloat16* Bs = (__nv_bfloat16*)(smem + SM_B);
    float* sc   = (float*)(smem + SM_SC);
    float* wns  = (float*)(smem + SM_WNS);
    float* rv   = (float*)(smem + SM_RV);
    float* r2   = (float*)(smem + SM_R2);
    int*   ri   = (int*)  (smem + SM_RI);
    int*   idxs = (int*)  (smem + SM_IDX);
    int*   flg  = (int*)  (smem + SM_FLG);

    const int tid = threadIdx.x;
    const int wid = tid >> 5;
    const int bm = blockIdx.x * BM;

    for (int e = tid; e < NPROTO; e += 256) wns[e] = g_wn[e];
    stage_bf16(As, (const float4*)x, (size_t)bm, tid);   // A = x tile
    stage_bf16(Bs, (const float4*)pw, 0, tid);           // B = proto tile 0
    __syncthreads();

    // persistent per-thread running argmin: row = tid>>1, half = tid&1
    const int r_row = tid >> 1;
    const int half = tid & 1;
    const int scw = (r_row >> 5) * 2 + half;   // warp tile holding (row, half)
    const int lr = r_row & 31;
    float B1 = 3.0e38f, B2 = 3.0e38f;
    int I1 = 0;

    const int wm = wid >> 1;     // warp row group (0..3) -> rows 32*wm
    const int wn = wid & 1;      // warp col group (0..1) -> cols 64*wn

    for (int nt = 0; nt < 4; nt++) {
        // ---- wmma: 32x64 per warp = 2x4 fragments, K = 16 steps ----
        wmma::fragment<wmma::accumulator, 16, 16, 16, float> acc[2][4];
        #pragma unroll
        for (int mi = 0; mi < 2; mi++)
            #pragma unroll
            for (int ni = 0; ni < 4; ni++) wmma::fill_fragment(acc[mi][ni], 0.0f);

        #pragma unroll
        for (int k = 0; k < 16; k++) {
            wmma::fragment<wmma::matrix_a, 16, 16, 16, __nv_bfloat16, wmma::row_major> af[2];
            wmma::fragment<wmma::matrix_b, 16, 16, 16, __nv_bfloat16, wmma::col_major> bf[4];
            #pragma unroll
            for (int mi = 0; mi < 2; mi++)
                wmma::load_matrix_sync(af[mi], As + (wm * 32 + mi * 16) * ASTR + k * 16, ASTR);
            #pragma unroll
            for (int ni = 0; ni < 4; ni++)   // col-major B: (k,n) at Bs[n*ASTR + k]
                wmma::load_matrix_sync(bf[ni], Bs + (wn * 64 + ni * 16) * ASTR + k * 16, ASTR);
            #pragma unroll
            for (int mi = 0; mi < 2; mi++)
                #pragma unroll
                for (int ni = 0; ni < 4; ni++)
                    wmma::mma_sync(acc[mi][ni], af[mi], bf[ni], acc[mi][ni]);
        }
        // dump scores: warp region sc[wid][0..31][0..63], ld = SSTR
        #pragma unroll
        for (int mi = 0; mi < 2; mi++)
            #pragma unroll
            for (int ni = 0; ni < 4; ni++)
                wmma::store_matrix_sync(sc + (size_t)wid * 32 * SSTR + mi * 16 * SSTR + ni * 16,
                                        acc[mi][ni], SSTR, wmma::mem_row_major);
        __syncthreads();

        // ---- argmin scan: score = wn[j] - 2*dot ----
        {
            const float* row = sc + (size_t)scw * 32 * SSTR + lr * SSTR;
            const int j0 = nt * 128 + half * 64;
            #pragma unroll 8
            for (int c = 0; c < 64; c++) {
                float s = fmaf(-2.f, row[c], wns[j0 + c]);
                if (s < B1) { B2 = B1; B1 = s; I1 = j0 + c; }
                else if (s < B2) B2 = s;
            }
        }
        // restage B for next n-tile (overlaps nothing dangerous; synced below)
        if (nt < 3)
            stage_bf16(Bs, (const float4*)pw, (size_t)(nt + 1) * 128, tid);
        __syncthreads();
    }

    // combine the two half-threads per row
    rv[tid] = B1; r2[tid] = B2; ri[tid] = I1;
    __syncthreads();
    if (tid < BM) {
        float v0 = rv[tid * 2], v1 = rv[tid * 2 + 1];
        int   i0 = ri[tid * 2], i1 = ri[tid * 2 + 1];
        float B1f, B2f; int I1f;
        if (v1 < v0 || (v1 == v0 && i1 < i0)) {
            B1f = v1; I1f = i1; B2f = fminf(v0, r2[tid * 2 + 1]);
        } else {
            B1f = v0; I1f = i0; B2f = fminf(v1, r2[tid * 2]);
        }
        idxs[tid] = I1f;
        int f = (B2f - B1f < TAU) ? 1 : 0;
        flg[tid] = f;
        if (f) g_flaglist[atomicAdd(&g_nflag, 1)] = bm + tid;
    }
    __syncthreads();

    // ---- epilogue: reload x fp32, gather proto, write outputs, loss partial ----
    float lsum = 0.f;
    float4* outP = (float4*)out;
    float4* outX = outP + TDTOT / 4;
    const float4* w4 = (const float4*)pw;
    const float4* x4 = (const float4*)x;
    for (int e = tid; e < BM * 64; e += 256) {
        int r = e >> 6, c4 = e & 63;
        int j = idxs[r];
        float4 wv = __ldg(&w4[(size_t)j * 64 + c4]);
        float4 xv = x4[(size_t)(bm + r) * 64 + c4];
        size_t o = (size_t)(bm + r) * 64 + c4;
        outP[o] = wv;
        float4 dx;
        dx.x = xv.x - wv.x; dx.y = xv.y - wv.y;
        dx.z = xv.z - wv.z; dx.w = xv.w - wv.w;
        outX[o] = dx;
        if (!flg[r]) lsum += dx.x * dx.x + dx.y * dx.y + dx.z * dx.z + dx.w * dx.w;
    }
    #pragma unroll
    for (int s = 16; s > 0; s >>= 1) lsum += __shfl_down_sync(0xffffffffu, lsum, s);
    __syncthreads();
    if ((tid & 31) == 0) rv[wid] = lsum;
    __syncthreads();
    if (tid == 0) {
        float t = 0.f;
        #pragma unroll
        for (int w = 0; w < 8; w++) t += rv[w];
        g_partials[blockIdx.x] = t;
    }
}

// ---- phase 2: flagged tokens. fp32 full rescore (batched 8/block) ->
//      shortlist -> fp64 + reference-fp32-rounding emulation on candidates ----
__global__ __launch_bounds__(256) void fix_ties(const float* __restrict__ x,
                                                const float* __restrict__ pw,
                                                float* __restrict__ out) {
    __shared__ float xs[FIXB][Dd];
    __shared__ float sc[FIXB][NPROTO];
    __shared__ float rmin[256];
    __shared__ double dred[8];
    __shared__ float sxs[FIXB];
    __shared__ int clist[FIXB][MAXC];
    __shared__ float cfd[FIXB][MAXC];
    __shared__ int ccnt[FIXB];
    __shared__ int jbest[FIXB];

    const int tid = threadIdx.x;
    const int lane = tid & 31, wrp = tid >> 5;
    const int nf = g_nflag;
    const int nb = (nf + FIXB - 1) / FIXB;

    for (int b = blockIdx.x; b < nb; b += gridDim.x) {
        const int base = b * FIXB;
        const int m = min(FIXB, nf - base);
        for (int e = tid; e < m * Dd; e += 256) {
            int i = e >> 8, k = e & 255;
            xs[i][k] = x[(size_t)g_flaglist[base + i] * Dd + k];
        }
        __syncthreads();

        float a0[FIXB], a1[FIXB];
        #pragma unroll
        for (int i = 0; i < FIXB; i++) { a0[i] = 0.f; a1[i] = 0.f; }
        const float4* w4 = (const float4*)pw;
        for (int k4 = 0; k4 < 64; k4++) {
            float4 wa = w4[(size_t)tid * 64 + k4];
            float4 wb = w4[(size_t)(tid + 256) * 64 + k4];
            #pragma unroll
            for (int i = 0; i < FIXB; i++) {
                float x0 = xs[i][k4 * 4], x1 = xs[i][k4 * 4 + 1];
                float x2 = xs[i][k4 * 4 + 2], x3 = xs[i][k4 * 4 + 3];
                a0[i] = fmaf(x0, wa.x, a0[i]); a0[i] = fmaf(x1, wa.y, a0[i]);
                a0[i] = fmaf(x2, wa.z, a0[i]); a0[i] = fmaf(x3, wa.w, a0[i]);
                a1[i] = fmaf(x0, wb.x, a1[i]); a1[i] = fmaf(x1, wb.y, a1[i]);
                a1[i] = fmaf(x2, wb.z, a1[i]); a1[i] = fmaf(x3, wb.w, a1[i]);
            }
        }
        float wn0 = g_wn[tid], wn1 = g_wn[tid + 256];
        #pragma unroll
        for (int i = 0; i < FIXB; i++) {
            sc[i][tid] = wn0 - 2.f * a0[i];
            sc[i][tid + 256] = wn1 - 2.f * a1[i];
        }
        __syncthreads();

        for (int i = 0; i < m; i++) {
            rmin[tid] = fminf(sc[i][tid], sc[i][tid + 256]);
            __syncthreads();
            for (int s = 128; s > 0; s >>= 1) {
                if (tid < s) rmin[tid] = fminf(rmin[tid], rmin[tid + s]);
                __syncthreads();
            }
            float B1 = rmin[0];
            if (tid == 0) ccnt[i] = 0;
            __syncthreads();
            if (sc[i][tid] < B1 + CAND_CUT) {
                int s = atomicAdd(&ccnt[i], 1);
                if (s < MAXC) clist[i][s] = tid;
            }
            if (sc[i][tid + 256] < B1 + CAND_CUT) {
                int s = atomicAdd(&ccnt[i], 1);
                if (s < MAXC) clist[i][s] = tid + 256;
            }
            double px = (double)xs[i][tid] * (double)xs[i][tid];
            #pragma unroll
            for (int s = 16; s > 0; s >>= 1) px += __shfl_down_sync(0xffffffffu, px, s);
            if (lane == 0) dred[wrp] = px;
            __syncthreads();
            if (tid == 0) {
                double t = 0.0;
                #pragma unroll
                for (int w = 0; w < 8; w++) t += dred[w];
                sxs[i] = (float)t;
            }
            __syncthreads();
            int nc = min(ccnt[i], MAXC);
            for (int c = wrp; c < nc; c += 8) {
                int j = clist[i][c];
                const float* wr = pw + (size_t)j * Dd;
                double d = 0.0;
                for (int k = lane; k < Dd; k += 32)
                    d += (double)xs[i][k] * (double)wr[k];
                #pragma unroll
                for (int s = 16; s > 0; s >>= 1) d += __shfl_down_sync(0xffffffffu, d, s);
                if (lane == 0)
                    cfd[i][c] = __fsub_rn(__fadd_rn(sxs[i], g_wn[j]), 2.0f * (float)d);
            }
            __syncthreads();
            if (tid == 0) {
                float bv = 3.0e38f; int bj = 0x7fffffff;
                for (int c = 0; c < nc; c++) {
                    float v = cfd[i][c]; int j = clist[i][c];
                    if (v < bv || (v == bv && j < bj)) { bv = v; bj = j; }
                }
                jbest[i] = (nc > 0) ? bj : 0;
            }
            __syncthreads();
        }
        for (int i = 0; i < m; i++) {
            int t = g_flaglist[base + i];
            int j = jbest[i];
            float wv = pw[(size_t)j * Dd + tid];
            float xv = xs[i][tid];
            out[(size_t)t * Dd + tid] = wv;
            float dx = xv - wv;
            out[TDTOT + (size_t)t * Dd + tid] = dx;
            rmin[tid] = dx * dx;
            __syncthreads();
            for (int s = 128; s > 0; s >>= 1) {
                if (tid < s) rmin[tid] += rmin[tid + s];
                __syncthreads();
            }
            if (tid == 0) g_extra[t] = rmin[0];
            __syncthreads();
        }
    }
}

// ---- parallel reduction of g_extra (deterministic, token-ordered) ----
__global__ void reduce_extra() {
    __shared__ float s[256];
    int tid = threadIdx.x;
    int base = blockIdx.x * 512;
    s[tid] = g_extra[base + tid] + g_extra[base + 256 + tid];
    __syncthreads();
    for (int st = 128; st > 0; st >>= 1) {
        if (tid < st) s[tid] += s[tid + st];
        __syncthreads();
    }
    if (tid == 0) g_epart[blockIdx.x] = s[0];
}

__global__ void finalize_loss(float* __restrict__ out) {
    __shared__ float s[256];
    int tid = threadIdx.x;
    float v = 0.f;
    for (int t = tid; t < NBLK; t += 256) v += g_partials[t];
    if (tid < 256) v += g_epart[tid];
    s[tid] = v;
    __syncthreads();
    for (int st = 128; st > 0; st >>= 1) {
        if (tid < st) s[tid] += s[tid + st];
        __syncthreads();
    }
    if (tid == 0) out[2 * TDTOT] = s[0] * (1.25f / (float)TDTOT);
}

extern "C" void kernel_launch(void* const* d_in, const int* in_sizes, int n_in,
                              void* d_out, int out_size) {
    const float* x  = (const float*)d_in[0];
    const float* pw = (const float*)d_in[1];
    float* out = (float*)d_out;

    cudaFuncSetAttribute(vq_main, cudaFuncAttributeMaxDynamicSharedMemorySize, SMEMB);
    wn_kernel<<<2, 256>>>(pw);
    vq_main<<<NBLK, 256, SMEMB>>>(x, pw, out);
    fix_ties<<<512, 256>>>(x, pw, out);
    reduce_extra<<<256, 256>>>();
    finalize_loss<<<1, 256>>>(out);
}

// round 6
// speedup vs baseline: 2.2500x; 1.0547x over previous
#include <cuda_runtime.h>
#include <cuda_bf16.h>
#include <cstdint>

#define T_TOK 131072
#define Dd 256
#define NPROTO 512
#define BM 128
#define NBLK (T_TOK / BM)           // 1024
#define TDTOT ((size_t)T_TOK * Dd)  // 33554432
#define TAU 0.5f
#define CAND_CUT 2e-3f
#define FIXB 8
#define MAXC 16

#define ASTR 264                    // row stride in bf16 (528B = 33*16B)
#define CHB 33792                   // 64 rows * 528B  (one B chunk)

// smem byte offsets
#define SM_A    0                   // 128*528 = 67584
#define SM_B    67584               // 2 chunks * 33792 = 67584
#define SM_WNS  135168              // 2048
#define SM_RV   137216              // 512
#define SM_R2   137728              // 512
#define SM_RI   138240              // 512
#define SM_IDX  138752              // 512
#define SM_FLG  139264              // 512
#define SMEMB   139776

typedef unsigned int u32;

__device__ float g_wn[NPROTO];
__device__ __align__(16) __nv_bfloat16 g_wbf[NPROTO * ASTR];  // W pre-converted, smem layout
__device__ float g_partials[NBLK];
__device__ float g_epart[256];
__device__ float g_extra[T_TOK];
__device__ int   g_flaglist[T_TOK];
__device__ int   g_nflag;

__device__ __forceinline__ u32 smem_u32(const void* p) {
    u32 a;
    asm("{ .reg .u64 t; cvta.to.shared.u64 t, %1; cvt.u32.u64 %0, t; }" : "=r"(a) : "l"(p));
    return a;
}
__device__ __forceinline__ void cp16(u32 dst, const void* src) {
    asm volatile("cp.async.ca.shared.global [%0], [%1], 16;" :: "r"(dst), "l"(src));
}
#define CP_COMMIT() asm volatile("cp.async.commit_group;" ::: "memory")
#define CP_WAIT0()  asm volatile("cp.async.wait_group 0;" ::: "memory")

__device__ __forceinline__ void ldm_x4(u32 addr, u32& r0, u32& r1, u32& r2, u32& r3) {
    asm volatile("ldmatrix.sync.aligned.m8n8.x4.shared.b16 {%0,%1,%2,%3}, [%4];"
                 : "=r"(r0), "=r"(r1), "=r"(r2), "=r"(r3) : "r"(addr));
}
__device__ __forceinline__ void mma_bf16(float* d, u32 a0, u32 a1, u32 a2, u32 a3,
                                         u32 b0, u32 b1) {
    asm volatile(
        "mma.sync.aligned.m16n8k16.row.col.f32.bf16.bf16.f32 "
        "{%0,%1,%2,%3}, {%4,%5,%6,%7}, {%8,%9}, {%0,%1,%2,%3};"
        : "+f"(d[0]), "+f"(d[1]), "+f"(d[2]), "+f"(d[3])
        : "r"(a0), "r"(a1), "r"(a2), "r"(a3), "r"(b0), "r"(b1));
}

// Stage a 128x256 fp32 tile as bf16 rows (stride ASTR) into smem.
__device__ __forceinline__ void stage_bf16(__nv_bfloat16* dst, const float4* __restrict__ s4,
                                           size_t row0, int tid) {
    for (int e = tid; e < 4096; e += 256) {
        int r = e >> 5, c8 = e & 31;
        const float4* p = s4 + (row0 + r) * 64 + c8 * 2;
        float4 a = p[0], b = p[1];
        __nv_bfloat162 q0 = __floats2bfloat162_rn(a.x, a.y);
        __nv_bfloat162 q1 = __floats2bfloat162_rn(a.z, a.w);
        __nv_bfloat162 q2 = __floats2bfloat162_rn(b.x, b.y);
        __nv_bfloat162 q3 = __floats2bfloat162_rn(b.z, b.w);
        uint4 v;
        v.x = *(u32*)&q0; v.y = *(u32*)&q1; v.z = *(u32*)&q2; v.w = *(u32*)&q3;
        *(uint4*)(dst + r * ASTR + c8 * 8) = v;
    }
}

// ---- ||w||^2 + bf16 copy of W in smem-tile layout + counter reset ----
__global__ void wn_kernel(const float* __restrict__ pw) {
    int j = blockIdx.x * blockDim.x + threadIdx.x;
    if (j == 0) g_nflag = 0;
    if (j < NPROTO) {
        const float* r = pw + (size_t)j * Dd;
        double s = 0.0;
        #pragma unroll 8
        for (int k = 0; k < Dd; k++) {
            float v = r[k];
            s += (double)v * (double)v;
            g_wbf[j * ASTR + k] = __float2bfloat16(v);
        }
        #pragma unroll
        for (int k = Dd; k < ASTR; k++) g_wbf[j * ASTR + k] = __float2bfloat16(0.f);
        g_wn[j] = (float)s;
    }
}

__device__ __forceinline__ void upd(float s, int j, float& b1, float& b2, int& i1) {
    if (s < b1) { b2 = b1; b1 = s; i1 = j; }
    else if (s < b2) b2 = s;
}

// ---- main fused kernel ----
__global__ __launch_bounds__(256) void vq_main(const float* __restrict__ x,
                                               const float* __restrict__ pw,
                                               float* __restrict__ out) {
    extern __shared__ char smem[];
    const u32 sb = smem_u32(smem);
    float* wns  = (float*)(smem + SM_WNS);
    float* rv   = (float*)(smem + SM_RV);
    float* r2s  = (float*)(smem + SM_R2);
    int*   ris  = (int*)  (smem + SM_RI);
    int*   idxs = (int*)  (smem + SM_IDX);
    int*   flg  = (int*)  (smem + SM_FLG);

    const int tid = threadIdx.x;
    const int wid = tid >> 5;
    const int lane = tid & 31;
    const int bm = blockIdx.x * BM;

    // prefetch B chunk 0 (64 protos) via cp.async from pre-converted bf16 W
    {
        const char* src = (const char*)g_wbf;
        for (int e = tid; e < CHB / 16; e += 256)
            cp16(sb + SM_B + e * 16, src + e * 16);
        CP_COMMIT();
    }
    for (int e = tid; e < NPROTO; e += 256) wns[e] = g_wn[e];
    stage_bf16((__nv_bfloat16*)(smem + SM_A), (const float4*)x, (size_t)bm, tid);
    CP_WAIT0();
    __syncthreads();

    // preload all A fragments: warp rows = wid*16..+15, 16 k-tiles, 4 regs each
    u32 A[16][4];
    {
        const u32 arow = wid * 16 + ((lane >> 3) & 1) * 8 + (lane & 7);
        const u32 akoff = (lane >> 4) * 8;
        #pragma unroll
        for (int kt = 0; kt < 16; kt++) {
            u32 addr = sb + SM_A + (arow * ASTR + kt * 16 + akoff) * 2;
            ldm_x4(addr, A[kt][0], A[kt][1], A[kt][2], A[kt][3]);
        }
    }

    // running argmin state: rows g = lane/4 and g+8 of this warp's 16-row slice
    const int th = lane & 3;
    float b1a = 3.0e38f, b2a = 3.0e38f; int i1a = 0;   // row g
    float b1b = 3.0e38f, b2b = 3.0e38f; int i1b = 0;   // row g+8

    const u32 brow = ((lane >> 4) * 8 + (lane & 7));
    const u32 bkoff = ((lane >> 3) & 1) * 8;

    for (int c = 0; c < 8; c++) {
        if (c < 7) {   // prefetch next chunk into other buffer
            const char* src = (const char*)g_wbf + (size_t)(c + 1) * CHB;
            u32 dst = sb + SM_B + ((c + 1) & 1) * CHB;
            for (int e = tid; e < CHB / 16; e += 256)
                cp16(dst + e * 16, src + e * 16);
            CP_COMMIT();
        }
        // compute on chunk c
        float acc[8][4];
        #pragma unroll
        for (int i = 0; i < 8; i++)
            #pragma unroll
            for (int q = 0; q < 4; q++) acc[i][q] = 0.f;

        const u32 bbase = sb + SM_B + (c & 1) * CHB;
        #pragma unroll
        for (int kt = 0; kt < 16; kt++) {
            #pragma unroll
            for (int ni = 0; ni < 4; ni++) {
                u32 b0, b1, b2, b3;
                u32 addr = bbase + (((ni * 16 + brow) * ASTR) + kt * 16 + bkoff) * 2;
                ldm_x4(addr, b0, b1, b2, b3);
                mma_bf16(acc[ni * 2],     A[kt][0], A[kt][1], A[kt][2], A[kt][3], b0, b1);
                mma_bf16(acc[ni * 2 + 1], A[kt][0], A[kt][1], A[kt][2], A[kt][3], b2, b3);
            }
        }
        // argmin update straight from accumulators
        #pragma unroll
        for (int i = 0; i < 8; i++) {
            const int jb = c * 64 + i * 8 + th * 2;
            float s;
            s = fmaf(-2.f, acc[i][0], wns[jb]);     upd(s, jb,     b1a, b2a, i1a);
            s = fmaf(-2.f, acc[i][1], wns[jb + 1]); upd(s, jb + 1, b1a, b2a, i1a);
            s = fmaf(-2.f, acc[i][2], wns[jb]);     upd(s, jb,     b1b, b2b, i1b);
            s = fmaf(-2.f, acc[i][3], wns[jb + 1]); upd(s, jb + 1, b1b, b2b, i1b);
        }
        if (c < 7) { CP_WAIT0(); __syncthreads(); }
    }

    // quad-merge (lanes sharing a row differ in bits 0-1)
    #pragma unroll
    for (int off = 1; off <= 2; off <<= 1) {
        float ov, o2; int oi;
        ov = __shfl_xor_sync(0xffffffffu, b1a, off);
        o2 = __shfl_xor_sync(0xffffffffu, b2a, off);
        oi = __shfl_xor_sync(0xffffffffu, i1a, off);
        if (ov < b1a || (ov == b1a && oi < i1a)) { b2a = fminf(b1a, o2); b1a = ov; i1a = oi; }
        else b2a = fminf(b2a, ov);
        ov = __shfl_xor_sync(0xffffffffu, b1b, off);
        o2 = __shfl_xor_sync(0xffffffffu, b2b, off);
        oi = __shfl_xor_sync(0xffffffffu, i1b, off);
        if (ov < b1b || (ov == b1b && oi < i1b)) { b2b = fminf(b1b, o2); b1b = ov; i1b = oi; }
        else b2b = fminf(b2b, ov);
    }
    if (th == 0) {
        int g = lane >> 2;
        int ra = wid * 16 + g, rb = ra + 8;
        rv[ra] = b1a; r2s[ra] = b2a; ris[ra] = i1a;
        rv[rb] = b1b; r2s[rb] = b2b; ris[rb] = i1b;
    }
    __syncthreads();
    if (tid < BM) {
        float B1 = rv[tid], B2 = r2s[tid];
        int I1 = ris[tid];
        idxs[tid] = I1;
        int f = (B2 - B1 < TAU) ? 1 : 0;
        flg[tid] = f;
        if (f) g_flaglist[atomicAdd(&g_nflag, 1)] = bm + tid;
    }
    __syncthreads();

    // epilogue
    float lsum = 0.f;
    float4* outP = (float4*)out;
    float4* outX = outP + TDTOT / 4;
    const float4* w4 = (const float4*)pw;
    const float4* x4 = (const float4*)x;
    for (int e = tid; e < BM * 64; e += 256) {
        int r = e >> 6, c4 = e & 63;
        int j = idxs[r];
        float4 wv = __ldg(&w4[(size_t)j * 64 + c4]);
        float4 xv = x4[(size_t)(bm + r) * 64 + c4];
        size_t o = (size_t)(bm + r) * 64 + c4;
        outP[o] = wv;
        float4 dx;
        dx.x = xv.x - wv.x; dx.y = xv.y - wv.y;
        dx.z = xv.z - wv.z; dx.w = xv.w - wv.w;
        outX[o] = dx;
        if (!flg[r]) lsum += dx.x * dx.x + dx.y * dx.y + dx.z * dx.z + dx.w * dx.w;
    }
    #pragma unroll
    for (int s = 16; s > 0; s >>= 1) lsum += __shfl_down_sync(0xffffffffu, lsum, s);
    __syncthreads();
    if ((tid & 31) == 0) rv[wid] = lsum;
    __syncthreads();
    if (tid == 0) {
        float t = 0.f;
        #pragma unroll
        for (int w = 0; w < 8; w++) t += rv[w];
        g_partials[blockIdx.x] = t;
    }
}

// ---- phase 2: flagged tokens (unchanged, proven) ----
__global__ __launch_bounds__(256) void fix_ties(const float* __restrict__ x,
                                                const float* __restrict__ pw,
                                                float* __restrict__ out) {
    __shared__ float xs[FIXB][Dd];
    __shared__ float sc[FIXB][NPROTO];
    __shared__ float rmin[256];
    __shared__ double dred[8];
    __shared__ float sxs[FIXB];
    __shared__ int clist[FIXB][MAXC];
    __shared__ float cfd[FIXB][MAXC];
    __shared__ int ccnt[FIXB];
    __shared__ int jbest[FIXB];

    const int tid = threadIdx.x;
    const int lane = tid & 31, wrp = tid >> 5;
    const int nf = g_nflag;
    const int nb = (nf + FIXB - 1) / FIXB;

    for (int b = blockIdx.x; b < nb; b += gridDim.x) {
        const int base = b * FIXB;
        const int m = min(FIXB, nf - base);
        for (int e = tid; e < m * Dd; e += 256) {
            int i = e >> 8, k = e & 255;
            xs[i][k] = x[(size_t)g_flaglist[base + i] * Dd + k];
        }
        __syncthreads();

        float a0[FIXB], a1[FIXB];
        #pragma unroll
        for (int i = 0; i < FIXB; i++) { a0[i] = 0.f; a1[i] = 0.f; }
        const float4* w4 = (const float4*)pw;
        for (int k4 = 0; k4 < 64; k4++) {
            float4 wa = w4[(size_t)tid * 64 + k4];
            float4 wb = w4[(size_t)(tid + 256) * 64 + k4];
            #pragma unroll
            for (int i = 0; i < FIXB; i++) {
                float x0 = xs[i][k4 * 4], x1 = xs[i][k4 * 4 + 1];
                float x2 = xs[i][k4 * 4 + 2], x3 = xs[i][k4 * 4 + 3];
                a0[i] = fmaf(x0, wa.x, a0[i]); a0[i] = fmaf(x1, wa.y, a0[i]);
                a0[i] = fmaf(x2, wa.z, a0[i]); a0[i] = fmaf(x3, wa.w, a0[i]);
                a1[i] = fmaf(x0, wb.x, a1[i]); a1[i] = fmaf(x1, wb.y, a1[i]);
                a1[i] = fmaf(x2, wb.z, a1[i]); a1[i] = fmaf(x3, wb.w, a1[i]);
            }
        }
        float wn0 = g_wn[tid], wn1 = g_wn[tid + 256];
        #pragma unroll
        for (int i = 0; i < FIXB; i++) {
            sc[i][tid] = wn0 - 2.f * a0[i];
            sc[i][tid + 256] = wn1 - 2.f * a1[i];
        }
        __syncthreads();

        for (int i = 0; i < m; i++) {
            rmin[tid] = fminf(sc[i][tid], sc[i][tid + 256]);
            __syncthreads();
            for (int s = 128; s > 0; s >>= 1) {
                if (tid < s) rmin[tid] = fminf(rmin[tid], rmin[tid + s]);
                __syncthreads();
            }
            float B1 = rmin[0];
            if (tid == 0) ccnt[i] = 0;
            __syncthreads();
            if (sc[i][tid] < B1 + CAND_CUT) {
                int s = atomicAdd(&ccnt[i], 1);
                if (s < MAXC) clist[i][s] = tid;
            }
            if (sc[i][tid + 256] < B1 + CAND_CUT) {
                int s = atomicAdd(&ccnt[i], 1);
                if (s < MAXC) clist[i][s] = tid + 256;
            }
            double px = (double)xs[i][tid] * (double)xs[i][tid];
            #pragma unroll
            for (int s = 16; s > 0; s >>= 1) px += __shfl_down_sync(0xffffffffu, px, s);
            if (lane == 0) dred[wrp] = px;
            __syncthreads();
            if (tid == 0) {
                double t = 0.0;
                #pragma unroll
                for (int w = 0; w < 8; w++) t += dred[w];
                sxs[i] = (float)t;
            }
            __syncthreads();
            int nc = min(ccnt[i], MAXC);
            for (int c = wrp; c < nc; c += 8) {
                int j = clist[i][c];
                const float* wr = pw + (size_t)j * Dd;
                double d = 0.0;
                for (int k = lane; k < Dd; k += 32)
                    d += (double)xs[i][k] * (double)wr[k];
                #pragma unroll
                for (int s = 16; s > 0; s >>= 1) d += __shfl_down_sync(0xffffffffu, d, s);
                if (lane == 0)
                    cfd[i][c] = __fsub_rn(__fadd_rn(sxs[i], g_wn[j]), 2.0f * (float)d);
            }
            __syncthreads();
            if (tid == 0) {
                float bv = 3.0e38f; int bj = 0x7fffffff;
                for (int c = 0; c < nc; c++) {
                    float v = cfd[i][c]; int j = clist[i][c];
                    if (v < bv || (v == bv && j < bj)) { bv = v; bj = j; }
                }
                jbest[i] = (nc > 0) ? bj : 0;
            }
            __syncthreads();
        }
        for (int i = 0; i < m; i++) {
            int t = g_flaglist[base + i];
            int j = jbest[i];
            float wv = pw[(size_t)j * Dd + tid];
            float xv = xs[i][tid];
            out[(size_t)t * Dd + tid] = wv;
            float dx = xv - wv;
            out[TDTOT + (size_t)t * Dd + tid] = dx;
            rmin[tid] = dx * dx;
            __syncthreads();
            for (int s = 128; s > 0; s >>= 1) {
                if (tid < s) rmin[tid] += rmin[tid + s];
                __syncthreads();
            }
            if (tid == 0) g_extra[t] = rmin[0];
            __syncthreads();
        }
    }
}

__global__ void reduce_extra() {
    __shared__ float s[256];
    int tid = threadIdx.x;
    int base = blockIdx.x * 512;
    s[tid] = g_extra[base + tid] + g_extra[base + 256 + tid];
    __syncthreads();
    for (int st = 128; st > 0; st >>= 1) {
        if (tid < st) s[tid] += s[tid + st];
        __syncthreads();
    }
    if (tid == 0) g_epart[blockIdx.x] = s[0];
}

__global__ void finalize_loss(float* __restrict__ out) {
    __shared__ float s[256];
    int tid = threadIdx.x;
    float v = 0.f;
    for (int t = tid; t < NBLK; t += 256) v += g_partials[t];
    if (tid < 256) v += g_epart[tid];
    s[tid] = v;
    __syncthreads();
    for (int st = 128; st > 0; st >>= 1) {
        if (tid < st) s[tid] += s[tid + st];
        __syncthreads();
    }
    if (tid == 0) out[2 * TDTOT] = s[0] * (1.25f / (float)TDTOT);
}

extern "C" void kernel_launch(void* const* d_in, const int* in_sizes, int n_in,
                              void* d_out, int out_size) {
    const float* x  = (const float*)d_in[0];
    const float* pw = (const float*)d_in[1];
    float* out = (float*)d_out;

    cudaFuncSetAttribute(vq_main, cudaFuncAttributeMaxDynamicSharedMemorySize, SMEMB);
    wn_kernel<<<2, 256>>>(pw);
    vq_main<<<NBLK, 256, SMEMB>>>(x, pw, out);
    fix_ties<<<512, 256>>>(x, pw, out);
    reduce_extra<<<256, 256>>>();
    finalize_loss<<<1, 256>>>(out);
}

// round 7
// speedup vs baseline: 2.4304x; 1.0802x over previous
#include <cuda_runtime.h>
#include <cuda_bf16.h>
#include <cstdint>

#define T_TOK 131072
#define Dd 256
#define NPROTO 512
#define BM 128
#define NBLK (T_TOK / BM)           // 1024
#define TDTOT ((size_t)T_TOK * Dd)  // 33554432
#define TAU 0.5f
#define CAND_CUT 2e-3f
#define FIXB 8
#define MAXC 16

#define ASTR 264                    // row stride in bf16 (528B = 33*16B)
#define CHP 32                      // protos per B chunk
#define NCH (NPROTO / CHP)          // 16 chunks
#define CHB (CHP * ASTR * 2)        // 16896 bytes per chunk

// smem byte offsets
#define SM_A    0                   // 128*528 = 67584
#define SM_B    67584               // 2 chunks * 16896 = 33792
#define SM_WNS  101376              // 2048
#define SM_RV   103424              // 512
#define SM_R2   103936              // 512
#define SM_RI   104448              // 512
#define SM_IDX  104960              // 512
#define SM_FLG  105472              // 512
#define SMEMB   105984

typedef unsigned int u32;

__device__ float g_wn[NPROTO];
__device__ __align__(16) __nv_bfloat16 g_wbf[NPROTO * ASTR];  // W pre-converted
__device__ float g_partials[NBLK];
__device__ float g_epart[256];
__device__ float g_extra[T_TOK];
__device__ int   g_flaglist[T_TOK];
__device__ int   g_nflag;

__device__ __forceinline__ u32 smem_u32(const void* p) {
    u32 a;
    asm("{ .reg .u64 t; cvta.to.shared.u64 t, %1; cvt.u32.u64 %0, t; }" : "=r"(a) : "l"(p));
    return a;
}
__device__ __forceinline__ void cp16(u32 dst, const void* src) {
    asm volatile("cp.async.ca.shared.global [%0], [%1], 16;" :: "r"(dst), "l"(src));
}
#define CP_COMMIT() asm volatile("cp.async.commit_group;" ::: "memory")
#define CP_WAIT0()  asm volatile("cp.async.wait_group 0;" ::: "memory")

__device__ __forceinline__ void ldm_x4(u32 addr, u32& r0, u32& r1, u32& r2, u32& r3) {
    asm volatile("ldmatrix.sync.aligned.m8n8.x4.shared.b16 {%0,%1,%2,%3}, [%4];"
                 : "=r"(r0), "=r"(r1), "=r"(r2), "=r"(r3) : "r"(addr));
}
__device__ __forceinline__ void mma_bf16(float* d, u32 a0, u32 a1, u32 a2, u32 a3,
                                         u32 b0, u32 b1) {
    asm volatile(
        "mma.sync.aligned.m16n8k16.row.col.f32.bf16.bf16.f32 "
        "{%0,%1,%2,%3}, {%4,%5,%6,%7}, {%8,%9}, {%0,%1,%2,%3};"
        : "+f"(d[0]), "+f"(d[1]), "+f"(d[2]), "+f"(d[3])
        : "r"(a0), "r"(a1), "r"(a2), "r"(a3), "r"(b0), "r"(b1));
}

// Stage a 128x256 fp32 tile as bf16 rows (stride ASTR) into smem.
__device__ __forceinline__ void stage_bf16(__nv_bfloat16* dst, const float4* __restrict__ s4,
                                           size_t row0, int tid) {
    for (int e = tid; e < 4096; e += 256) {
        int r = e >> 5, c8 = e & 31;
        const float4* p = s4 + (row0 + r) * 64 + c8 * 2;
        float4 a = p[0], b = p[1];
        __nv_bfloat162 q0 = __floats2bfloat162_rn(a.x, a.y);
        __nv_bfloat162 q1 = __floats2bfloat162_rn(a.z, a.w);
        __nv_bfloat162 q2 = __floats2bfloat162_rn(b.x, b.y);
        __nv_bfloat162 q3 = __floats2bfloat162_rn(b.z, b.w);
        uint4 v;
        v.x = *(u32*)&q0; v.y = *(u32*)&q1; v.z = *(u32*)&q2; v.w = *(u32*)&q3;
        *(uint4*)(dst + r * ASTR + c8 * 8) = v;
    }
}

// ---- ||w||^2 + bf16 copy of W + counter reset ----
__global__ void wn_kernel(const float* __restrict__ pw) {
    int j = blockIdx.x * blockDim.x + threadIdx.x;
    if (j == 0) g_nflag = 0;
    if (j < NPROTO) {
        const float* r = pw + (size_t)j * Dd;
        double s = 0.0;
        #pragma unroll 8
        for (int k = 0; k < Dd; k++) {
            float v = r[k];
            s += (double)v * (double)v;
            g_wbf[j * ASTR + k] = __float2bfloat16(v);
        }
        #pragma unroll
        for (int k = Dd; k < ASTR; k++) g_wbf[j * ASTR + k] = __float2bfloat16(0.f);
        g_wn[j] = (float)s;
    }
}

__device__ __forceinline__ void upd(float s, int j, float& b1, float& b2, int& i1) {
    if (s < b1) { b2 = b1; b1 = s; i1 = j; }
    else if (s < b2) b2 = s;
}

// ---- main fused kernel (2 CTAs/SM for phase overlap) ----
__global__ __launch_bounds__(256, 2) void vq_main(const float* __restrict__ x,
                                                  const float* __restrict__ pw,
                                                  float* __restrict__ out) {
    extern __shared__ char smem[];
    const u32 sb = smem_u32(smem);
    float* wns  = (float*)(smem + SM_WNS);
    float* rv   = (float*)(smem + SM_RV);
    float* r2s  = (float*)(smem + SM_R2);
    int*   ris  = (int*)  (smem + SM_RI);
    int*   idxs = (int*)  (smem + SM_IDX);
    int*   flg  = (int*)  (smem + SM_FLG);

    const int tid = threadIdx.x;
    const int wid = tid >> 5;
    const int lane = tid & 31;
    const int bm = blockIdx.x * BM;

    // prefetch B chunk 0 via cp.async from pre-converted bf16 W
    {
        const char* src = (const char*)g_wbf;
        for (int e = tid; e < CHB / 16; e += 256)
            cp16(sb + SM_B + e * 16, src + e * 16);
        CP_COMMIT();
    }
    for (int e = tid; e < NPROTO; e += 256) wns[e] = g_wn[e];
    stage_bf16((__nv_bfloat16*)(smem + SM_A), (const float4*)x, (size_t)bm, tid);
    CP_WAIT0();
    __syncthreads();

    // fragment address params (validated mapping from round 6)
    const u32 arow = wid * 16 + ((lane >> 3) & 1) * 8 + (lane & 7);
    const u32 akoff = (lane >> 4) * 8;
    const u32 brow = ((lane >> 4) * 8 + (lane & 7));
    const u32 bkoff = ((lane >> 3) & 1) * 8;

    // running argmin state: rows g = lane/4 and g+8 of this warp's 16-row slice
    const int th = lane & 3;
    float b1a = 3.0e38f, b2a = 3.0e38f; int i1a = 0;   // row g
    float b1b = 3.0e38f, b2b = 3.0e38f; int i1b = 0;   // row g+8

    for (int c = 0; c < NCH; c++) {
        if (c < NCH - 1) {   // prefetch next chunk into other buffer
            const char* src = (const char*)g_wbf + (size_t)(c + 1) * CHB;
            u32 dst = sb + SM_B + ((c + 1) & 1) * CHB;
            for (int e = tid; e < CHB / 16; e += 256)
                cp16(dst + e * 16, src + e * 16);
            CP_COMMIT();
        }
        float acc[4][4];
        #pragma unroll
        for (int i = 0; i < 4; i++)
            #pragma unroll
            for (int q = 0; q < 4; q++) acc[i][q] = 0.f;

        const u32 bbase = sb + SM_B + (c & 1) * CHB;
        #pragma unroll
        for (int kt = 0; kt < 16; kt++) {
            u32 a0, a1, a2, a3;
            ldm_x4(sb + SM_A + (arow * ASTR + kt * 16 + akoff) * 2, a0, a1, a2, a3);
            #pragma unroll
            for (int ni = 0; ni < 2; ni++) {
                u32 c0, c1, c2, c3;
                u32 addr = bbase + (((ni * 16 + brow) * ASTR) + kt * 16 + bkoff) * 2;
                ldm_x4(addr, c0, c1, c2, c3);
                mma_bf16(acc[ni * 2],     a0, a1, a2, a3, c0, c1);
                mma_bf16(acc[ni * 2 + 1], a0, a1, a2, a3, c2, c3);
            }
        }
        // argmin update straight from accumulators
        #pragma unroll
        for (int i = 0; i < 4; i++) {
            const int jb = c * CHP + i * 8 + th * 2;
            float s;
            s = fmaf(-2.f, acc[i][0], wns[jb]);     upd(s, jb,     b1a, b2a, i1a);
            s = fmaf(-2.f, acc[i][1], wns[jb + 1]); upd(s, jb + 1, b1a, b2a, i1a);
            s = fmaf(-2.f, acc[i][2], wns[jb]);     upd(s, jb,     b1b, b2b, i1b);
            s = fmaf(-2.f, acc[i][3], wns[jb + 1]); upd(s, jb + 1, b1b, b2b, i1b);
        }
        if (c < NCH - 1) { CP_WAIT0(); __syncthreads(); }
    }

    // quad-merge (lanes sharing a row differ in bits 0-1)
    #pragma unroll
    for (int off = 1; off <= 2; off <<= 1) {
        float ov, o2; int oi;
        ov = __shfl_xor_sync(0xffffffffu, b1a, off);
        o2 = __shfl_xor_sync(0xffffffffu, b2a, off);
        oi = __shfl_xor_sync(0xffffffffu, i1a, off);
        if (ov < b1a || (ov == b1a && oi < i1a)) { b2a = fminf(b1a, o2); b1a = ov; i1a = oi; }
        else b2a = fminf(b2a, ov);
        ov = __shfl_xor_sync(0xffffffffu, b1b, off);
        o2 = __shfl_xor_sync(0xffffffffu, b2b, off);
        oi = __shfl_xor_sync(0xffffffffu, i1b, off);
        if (ov < b1b || (ov == b1b && oi < i1b)) { b2b = fminf(b1b, o2); b1b = ov; i1b = oi; }
        else b2b = fminf(b2b, ov);
    }
    if (th == 0) {
        int g = lane >> 2;
        int ra = wid * 16 + g, rb = ra + 8;
        rv[ra] = b1a; r2s[ra] = b2a; ris[ra] = i1a;
        rv[rb] = b1b; r2s[rb] = b2b; ris[rb] = i1b;
    }
    __syncthreads();
    if (tid < BM) {
        float B1 = rv[tid], B2 = r2s[tid];
        int I1 = ris[tid];
        idxs[tid] = I1;
        int f = (B2 - B1 < TAU) ? 1 : 0;
        flg[tid] = f;
        if (f) g_flaglist[atomicAdd(&g_nflag, 1)] = bm + tid;
    }
    __syncthreads();

    // epilogue
    float lsum = 0.f;
    float4* outP = (float4*)out;
    float4* outX = outP + TDTOT / 4;
    const float4* w4 = (const float4*)pw;
    const float4* x4 = (const float4*)x;
    for (int e = tid; e < BM * 64; e += 256) {
        int r = e >> 6, c4 = e & 63;
        int j = idxs[r];
        float4 wv = __ldg(&w4[(size_t)j * 64 + c4]);
        float4 xv = x4[(size_t)(bm + r) * 64 + c4];
        size_t o = (size_t)(bm + r) * 64 + c4;
        outP[o] = wv;
        float4 dx;
        dx.x = xv.x - wv.x; dx.y = xv.y - wv.y;
        dx.z = xv.z - wv.z; dx.w = xv.w - wv.w;
        outX[o] = dx;
        if (!flg[r]) lsum += dx.x * dx.x + dx.y * dx.y + dx.z * dx.z + dx.w * dx.w;
    }
    #pragma unroll
    for (int s = 16; s > 0; s >>= 1) lsum += __shfl_down_sync(0xffffffffu, lsum, s);
    __syncthreads();
    if ((tid & 31) == 0) rv[wid] = lsum;
    __syncthreads();
    if (tid == 0) {
        float t = 0.f;
        #pragma unroll
        for (int w = 0; w < 8; w++) t += rv[w];
        g_partials[blockIdx.x] = t;
    }
}

// ---- phase 2: flagged tokens (unchanged, proven) ----
__global__ __launch_bounds__(256) void fix_ties(const float* __restrict__ x,
                                                const float* __restrict__ pw,
                                                float* __restrict__ out) {
    __shared__ float xs[FIXB][Dd];
    __shared__ float sc[FIXB][NPROTO];
    __shared__ float rmin[256];
    __shared__ double dred[8];
    __shared__ float sxs[FIXB];
    __shared__ int clist[FIXB][MAXC];
    __shared__ float cfd[FIXB][MAXC];
    __shared__ int ccnt[FIXB];
    __shared__ int jbest[FIXB];

    const int tid = threadIdx.x;
    const int lane = tid & 31, wrp = tid >> 5;
    const int nf = g_nflag;
    const int nb = (nf + FIXB - 1) / FIXB;

    for (int b = blockIdx.x; b < nb; b += gridDim.x) {
        const int base = b * FIXB;
        const int m = min(FIXB, nf - base);
        for (int e = tid; e < m * Dd; e += 256) {
            int i = e >> 8, k = e & 255;
            xs[i][k] = x[(size_t)g_flaglist[base + i] * Dd + k];
        }
        __syncthreads();

        float a0[FIXB], a1[FIXB];
        #pragma unroll
        for (int i = 0; i < FIXB; i++) { a0[i] = 0.f; a1[i] = 0.f; }
        const float4* w4 = (const float4*)pw;
        for (int k4 = 0; k4 < 64; k4++) {
            float4 wa = w4[(size_t)tid * 64 + k4];
            float4 wb = w4[(size_t)(tid + 256) * 64 + k4];
            #pragma unroll
            for (int i = 0; i < FIXB; i++) {
                float x0 = xs[i][k4 * 4], x1 = xs[i][k4 * 4 + 1];
                float x2 = xs[i][k4 * 4 + 2], x3 = xs[i][k4 * 4 + 3];
                a0[i] = fmaf(x0, wa.x, a0[i]); a0[i] = fmaf(x1, wa.y, a0[i]);
                a0[i] = fmaf(x2, wa.z, a0[i]); a0[i] = fmaf(x3, wa.w, a0[i]);
                a1[i] = fmaf(x0, wb.x, a1[i]); a1[i] = fmaf(x1, wb.y, a1[i]);
                a1[i] = fmaf(x2, wb.z, a1[i]); a1[i] = fmaf(x3, wb.w, a1[i]);
            }
        }
        float wn0 = g_wn[tid], wn1 = g_wn[tid + 256];
        #pragma unroll
        for (int i = 0; i < FIXB; i++) {
            sc[i][tid] = wn0 - 2.f * a0[i];
            sc[i][tid + 256] = wn1 - 2.f * a1[i];
        }
        __syncthreads();

        for (int i = 0; i < m; i++) {
            rmin[tid] = fminf(sc[i][tid], sc[i][tid + 256]);
            __syncthreads();
            for (int s = 128; s > 0; s >>= 1) {
                if (tid < s) rmin[tid] = fminf(rmin[tid], rmin[tid + s]);
                __syncthreads();
            }
            float B1 = rmin[0];
            if (tid == 0) ccnt[i] = 0;
            __syncthreads();
            if (sc[i][tid] < B1 + CAND_CUT) {
                int s = atomicAdd(&ccnt[i], 1);
                if (s < MAXC) clist[i][s] = tid;
            }
            if (sc[i][tid + 256] < B1 + CAND_CUT) {
                int s = atomicAdd(&ccnt[i], 1);
                if (s < MAXC) clist[i][s] = tid + 256;
            }
            double px = (double)xs[i][tid] * (double)xs[i][tid];
            #pragma unroll
            for (int s = 16; s > 0; s >>= 1) px += __shfl_down_sync(0xffffffffu, px, s);
            if (lane == 0) dred[wrp] = px;
            __syncthreads();
            if (tid == 0) {
                double t = 0.0;
                #pragma unroll
                for (int w = 0; w < 8; w++) t += dred[w];
                sxs[i] = (float)t;
            }
            __syncthreads();
            int nc = min(ccnt[i], MAXC);
            for (int c = wrp; c < nc; c += 8) {
                int j = clist[i][c];
                const float* wr = pw + (size_t)j * Dd;
                double d = 0.0;
                for (int k = lane; k < Dd; k += 32)
                    d += (double)xs[i][k] * (double)wr[k];
                #pragma unroll
                for (int s = 16; s > 0; s >>= 1) d += __shfl_down_sync(0xffffffffu, d, s);
                if (lane == 0)
                    cfd[i][c] = __fsub_rn(__fadd_rn(sxs[i], g_wn[j]), 2.0f * (float)d);
            }
            __syncthreads();
            if (tid == 0) {
                float bv = 3.0e38f; int bj = 0x7fffffff;
                for (int c = 0; c < nc; c++) {
                    float v = cfd[i][c]; int j = clist[i][c];
                    if (v < bv || (v == bv && j < bj)) { bv = v; bj = j; }
                }
                jbest[i] = (nc > 0) ? bj : 0;
            }
            __syncthreads();
        }
        for (int i = 0; i < m; i++) {
            int t = g_flaglist[base + i];
            int j = jbest[i];
            float wv = pw[(size_t)j * Dd + tid];
            float xv = xs[i][tid];
            out[(size_t)t * Dd + tid] = wv;
            float dx = xv - wv;
            out[TDTOT + (size_t)t * Dd + tid] = dx;
            rmin[tid] = dx * dx;
            __syncthreads();
            for (int s = 128; s > 0; s >>= 1) {
                if (tid < s) rmin[tid] += rmin[tid + s];
                __syncthreads();
            }
            if (tid == 0) g_extra[t] = rmin[0];
            __syncthreads();
        }
    }
}

__global__ void reduce_extra() {
    __shared__ float s[256];
    int tid = threadIdx.x;
    int base = blockIdx.x * 512;
    s[tid] = g_extra[base + tid] + g_extra[base + 256 + tid];
    __syncthreads();
    for (int st = 128; st > 0; st >>= 1) {
        if (tid < st) s[tid] += s[tid + st];
        __syncthreads();
    }
    if (tid == 0) g_epart[blockIdx.x] = s[0];
}

__global__ void finalize_loss(float* __restrict__ out) {
    __shared__ float s[256];
    int tid = threadIdx.x;
    float v = 0.f;
    for (int t = tid; t < NBLK; t += 256) v += g_partials[t];
    if (tid < 256) v += g_epart[tid];
    s[tid] = v;
    __syncthreads();
    for (int st = 128; st > 0; st >>= 1) {
        if (tid < st) s[tid] += s[tid + st];
        __syncthreads();
    }
    if (tid == 0) out[2 * TDTOT] = s[0] * (1.25f / (float)TDTOT);
}

extern "C" void kernel_launch(void* const* d_in, const int* in_sizes, int n_in,
                              void* d_out, int out_size) {
    const float* x  = (const float*)d_in[0];
    const float* pw = (const float*)d_in[1];
    float* out = (float*)d_out;

    cudaFuncSetAttribute(vq_main, cudaFuncAttributeMaxDynamicSharedMemorySize, SMEMB);
    wn_kernel<<<2, 256>>>(pw);
    vq_main<<<NBLK, 256, SMEMB>>>(x, pw, out);
    fix_ties<<<512, 256>>>(x, pw, out);
    reduce_extra<<<256, 256>>>();
    finalize_loss<<<1, 256>>>(out);
}